// round 10
// baseline (speedup 1.0000x reference)
#include <cuda_runtime.h>
#include <math.h>

#define Tt 64
#define Bb 256
#define Nn 256
#define Mm 128
#define Hh 1024
#define Ii 128
#define ICt 256
#define EPSf 1e-8f
#define NCTA 256
#define NTHR 256

// dynamic smem layout (floats)
#define W2F   16384          // P2 persistent W tile [1024 k][16 cols]
#define STGF  8320           // stage buffer: P1 uses [32x132 A | 128x32 Wc], P2 uses [32x260 A]
#define SMEMF (W2F + STGF)
#define SAS1  132            // P1 A row stride (128 floats + pad)
#define SAS2  260            // P2 A row stride (256 floats + pad)
#define WCOFF (32*SAS1)      // = 4224, Wc chunk offset inside stage

// ---------------- persistent device scratch ----------------
__device__ __align__(16) float g_mem[Bb*Nn*Mm];   // 33.5 MB, L2-resident
__device__ __align__(16) float g_ht [Bb*Hh];
__device__ __align__(16) float g_k  [2*Bb*Mm];
__device__ __align__(16) float g_e  [Bb*Mm];
__device__ __align__(16) float g_a  [Bb*Mm];
__device__ __align__(16) float g_rd [Bb*Mm];
__device__ unsigned g_barcnt;
__device__ volatile unsigned g_bargen;

// ---------------- f32x2 packed math ----------------
__device__ __forceinline__ unsigned long long pk2(float a){
    unsigned long long r;
    asm("mov.b64 %0,{%1,%1};" : "=l"(r) : "f"(a));
    return r;
}
__device__ __forceinline__ void f2fma(unsigned long long& c, unsigned long long a, unsigned long long b){
    asm("fma.rn.f32x2 %0,%1,%2,%0;" : "+l"(c) : "l"(a), "l"(b));
}
__device__ __forceinline__ unsigned long long ad2(unsigned long long a, unsigned long long b){
    unsigned long long r;
    asm("add.rn.f32x2 %0,%1,%2;" : "=l"(r) : "l"(a), "l"(b));
    return r;
}
__device__ __forceinline__ float2 up2(unsigned long long v){
    float2 f;
    asm("mov.b64 {%0,%1},%2;" : "=f"(f.x), "=f"(f.y) : "l"(v));
    return f;
}

// ---------------- grid barrier ----------------
__device__ __forceinline__ void gbar(){
    __threadfence();
    __syncthreads();
    if (threadIdx.x == 0){
        unsigned gen = g_bargen;
        if (atomicAdd(&g_barcnt, 1u) == NCTA - 1u){
            g_barcnt = 0u;
            __threadfence();
            g_bargen = gen + 1u;
        } else {
            while (g_bargen == gen) { __nanosleep(64); }
        }
        __threadfence();
    }
    __syncthreads();
}

// ---------------- block reductions ----------------
__device__ __forceinline__ float bredSum(float v, float* s_red){
    int lane = threadIdx.x & 31, wid = threadIdx.x >> 5;
    #pragma unroll
    for (int off = 16; off; off >>= 1) v += __shfl_xor_sync(0xffffffffu, v, off);
    if (lane == 0) s_red[wid] = v;
    __syncthreads();
    if (threadIdx.x == 0){
        float s = 0.f;
        #pragma unroll
        for (int j = 0; j < 8; j++) s += s_red[j];
        s_red[32] = s;
    }
    __syncthreads();
    return s_red[32];
}
__device__ __forceinline__ float bredMax(float v, float* s_red){
    int lane = threadIdx.x & 31, wid = threadIdx.x >> 5;
    #pragma unroll
    for (int off = 16; off; off >>= 1) v = fmaxf(v, __shfl_xor_sync(0xffffffffu, v, off));
    if (lane == 0) s_red[wid] = v;
    __syncthreads();
    if (threadIdx.x == 0){
        float s = -3.4e38f;
        #pragma unroll
        for (int j = 0; j < 8; j++) s = fmaxf(s, s_red[j]);
        s_red[32] = s;
    }
    __syncthreads();
    return s_red[32];
}

__device__ __forceinline__ float softplusf(float x){
    return fmaxf(x, 0.f) + log1pf(expf(-fabsf(x)));
}
__device__ __forceinline__ float sigmoidf_(float x){
    return 1.f / (1.f + expf(-x));
}

// ---------------- the persistent NTM kernel ----------------
__global__ void __launch_bounds__(NTHR, 2) ntm_kernel(
    const float* __restrict__ x,
    const float* __restrict__ Wc,   const float* __restrict__ bc,
    const float* __restrict__ Wk,   const float* __restrict__ bk,
    const float* __restrict__ Wb,   const float* __restrict__ bb,
    const float* __restrict__ Wg,   const float* __restrict__ bg,
    const float* __restrict__ Ws,   const float* __restrict__ bs,
    const float* __restrict__ Wgam, const float* __restrict__ bgam,
    const float* __restrict__ We,   const float* __restrict__ be,
    const float* __restrict__ Wa,   const float* __restrict__ ba,
    const float* __restrict__ Wo,   const float* __restrict__ bo,
    const float* __restrict__ memory0,
    const float* __restrict__ ww0,  const float* __restrict__ rw0,
    const float* __restrict__ read0,
    float* __restrict__ out)
{
    extern __shared__ __align__(16) float sm[];
    float* s_w2    = sm;            // 16384 floats, persistent P2 W tile
    float* s_stage = sm + W2F;      // 8320 floats
    float* s_wc    = s_stage + WCOFF;  // 4096 floats (P1 W chunk, aliased)

    __shared__ float s_ww[Nn];
    __shared__ float s_rw[Nn];
    __shared__ float s_nrm[Nn];     // inverse memory row norms (persist across t)
    __shared__ float s_red[40];
    __shared__ float s_sm[16];

    const int tid  = threadIdx.x;
    const int cta  = blockIdx.x;
    const int b    = cta;
    const int wid  = tid >> 5, lane = tid & 31;

    // ---- P1 tiling: 8 RB(32 rows) x 32 CB(32 cols) over [256,1024], k=256 ----
    const int RB1 = cta >> 5, CB1 = cta & 31;
    const int ks1 = tid >> 7, t7 = tid & 127;     // k-split 2
    const int rp1 = t7 >> 3, cq1 = t7 & 7;        // rows rp1 & rp1+16; cols cq1*4
    // ---- P2 tiling: 8 RB(32 rows) x 32 CB(16 cols) over [256,512], k=1024 ----
    const int RB2 = cta >> 5, CB2 = cta & 31;
    const int seg = CB2 >> 3;                     // which weight matrix
    const int c4b = (CB2 & 7) * 4;                // f4 col base within 128-wide segment
    const int g4  = tid >> 6, t6 = tid & 63;      // k-split 4
    const int rp2 = t6 >> 2, cq2 = t6 & 3;        // rows rp2 & rp2+16; cols cq2*4
    const float *Wp2, *bp2; float *op2;
    if      (seg == 0){ Wp2 = Wk;          bp2 = bk;      op2 = g_k; }
    else if (seg == 1){ Wp2 = Wk + Hh*Mm;  bp2 = bk + Mm; op2 = g_k + Bb*Mm; }
    else if (seg == 2){ Wp2 = We;          bp2 = be;      op2 = g_e; }
    else              { Wp2 = Wa;          bp2 = ba;      op2 = g_a; }

    // P3/P4 scratch carve inside s_stage
    float*  s_kw  = s_stage;                 // 128
    float*  s_kr  = s_stage + 128;           // 128
    float*  s_e   = s_stage + 256;           // 128
    float*  s_a   = s_stage + 384;           // 128
    float*  s_zw  = s_stage + 512;           // 256
    float*  s_zr  = s_stage + 768;           // 256
    float*  s_tmp = s_stage + 1024;          // 256
    float4* s_prd = (float4*)(s_stage + 1536); // 256 f4

    // ---------------- init ----------------
    {
        // persistent P2 W tile: [1024 k][16 cols]
        const float4* W4 = (const float4*)Wp2;
        for (int i = tid; i < 4096; i += NTHR){
            int k = i >> 2, jq = i & 3;
            *(float4*)&s_w2[k*16 + jq*4] = __ldg(&W4[k*32 + c4b + jq]);
        }
        float4*       md = ((float4*)g_mem) + b * (Nn*Mm/4);
        const float4* ms = (const float4*)memory0;
        for (int i = tid; i < Nn*Mm/4; i += NTHR) md[i] = ms[i];
        if (tid < Mm) __stcg(&g_rd[b*Mm + tid], read0[tid]);
        __syncthreads();
        // initial memory row inverse norms
        for (int j = 0; j < 32; j++){
            int n = wid*32 + j;
            float4 mv = md[n*32 + lane];
            float nn = mv.x*mv.x + mv.y*mv.y + mv.z*mv.z + mv.w*mv.w;
            #pragma unroll
            for (int off = 16; off; off >>= 1) nn += __shfl_xor_sync(0xffffffffu, nn, off);
            if (lane == 0) s_nrm[n] = 1.f / fmaxf(sqrtf(nn), EPSf);
        }
        float v  = ww0[tid];
        float mx = bredMax(v, s_red);
        float e  = expf(v - mx);
        float s  = bredSum(e, s_red);
        s_ww[tid] = e / s;
        v  = rw0[tid];
        mx = bredMax(v, s_red);
        e  = expf(v - mx);
        s  = bredSum(e, s_red);
        s_rw[tid] = e / s;
    }

    for (int t = 0; t < Tt; t++){
        gbar();   // prev-step rd globally visible

        // ================= P1: ht = tanh([x_t, rd] @ Wc + bc) =================
        {
            unsigned long long A00=0ull, A01=0ull, A10=0ull, A11=0ull;
            const float4* x4  = (const float4*)x;
            const float4* rd4 = (const float4*)g_rd;
            const float4* Wc4 = (const float4*)Wc;
            for (int c = 0; c < 2; c++){
                __syncthreads();
                // stage A chunk: 32 rows x 128 floats
                for (int i = tid; i < 32*32; i += NTHR){
                    int r = i >> 5, q = i & 31;
                    int row = RB1*32 + r;
                    float4 v;
                    if (c == 0) v = x4[(t*Bb + row)*32 + q];
                    else        v = __ldcg(&rd4[row*32 + q]);
                    *(float4*)&s_stage[r*SAS1 + q*4] = v;
                }
                // stage Wc chunk: 128 k x 32 cols
                for (int i = tid; i < 1024; i += NTHR){
                    int kk = i >> 3, jq = i & 7;
                    *(float4*)&s_wc[kk*32 + jq*4] = __ldg(&Wc4[(c*128 + kk)*256 + CB1*8 + jq]);
                }
                __syncthreads();
                const float* a0p = s_stage + rp1*SAS1 + ks1*64;
                const float* a1p = a0p + 16*SAS1;
                const float* wp  = s_wc + (ks1*64)*32 + cq1*4;
                #pragma unroll 8
                for (int kk = 0; kk < 64; kk++){
                    float a0 = a0p[kk], a1 = a1p[kk];
                    ulonglong2 w = *(const ulonglong2*)(wp + kk*32);
                    unsigned long long p0 = pk2(a0), p1 = pk2(a1);
                    f2fma(A00, p0, w.x); f2fma(A01, p0, w.y);
                    f2fma(A10, p1, w.x); f2fma(A11, p1, w.y);
                }
            }
            __syncthreads();
            unsigned long long* pp = (unsigned long long*)s_wc;
            if (ks1 == 1){
                pp[t7*4+0]=A00; pp[t7*4+1]=A01; pp[t7*4+2]=A10; pp[t7*4+3]=A11;
            }
            __syncthreads();
            if (ks1 == 0){
                A00 = ad2(A00, pp[t7*4+0]); A01 = ad2(A01, pp[t7*4+1]);
                A10 = ad2(A10, pp[t7*4+2]); A11 = ad2(A11, pp[t7*4+3]);
                float2 v00 = up2(A00), v01 = up2(A01), v10 = up2(A10), v11 = up2(A11);
                const int c4g = CB1*8 + cq1;
                float4 bi = __ldg(((const float4*)bc) + c4g);
                float4 o0 = make_float4(tanhf(v00.x+bi.x), tanhf(v00.y+bi.y),
                                        tanhf(v01.x+bi.z), tanhf(v01.y+bi.w));
                float4 o1 = make_float4(tanhf(v10.x+bi.x), tanhf(v10.y+bi.y),
                                        tanhf(v11.x+bi.z), tanhf(v11.y+bi.w));
                int row = RB1*32 + rp1;
                __stcg(((float4*)g_ht) + row*256 + c4g,      o0);
                __stcg(((float4*)g_ht) + (row+16)*256 + c4g, o1);
                // out[t-1] = rd_{t-1} @ Wo + bo : rd is the staged chunk-1 A-tile
                if (t > 0){
                    int r = tid >> 2, cc = tid & 3;
                    int col = CB1*4 + cc;
                    const float* ap = s_stage + r*SAS1;
                    float acc = 0.f;
                    #pragma unroll 8
                    for (int m = 0; m < 128; m++)
                        acc += ap[m] * __ldg(&Wo[m*Ii + col]);
                    out[(t-1)*(Bb*Ii) + (RB1*32 + r)*Ii + col] = acc + bo[col];
                }
            }
        }
        gbar();   // ht ready

        // ===== P2: [k_w|k_r|erase|add] = act(ht @ W + b), W resident in smem =====
        {
            unsigned long long A00=0ull, A01=0ull, A10=0ull, A11=0ull;
            const float4* ht4 = (const float4*)g_ht;
            for (int ch = 0; ch < 4; ch++){
                __syncthreads();
                for (int i = tid; i < 32*64; i += NTHR){
                    int r = i >> 6, q = i & 63;
                    float4 v = __ldcg(&ht4[(RB2*32 + r)*256 + ch*64 + q]);
                    *(float4*)&s_stage[r*SAS2 + q*4] = v;
                }
                __syncthreads();
                const float* a0p = s_stage + rp2*SAS2 + g4*64;
                const float* a1p = a0p + 16*SAS2;
                const float* wp  = s_w2 + (ch*256 + g4*64)*16 + cq2*4;
                #pragma unroll 8
                for (int kk = 0; kk < 64; kk++){
                    float a0 = a0p[kk], a1 = a1p[kk];
                    ulonglong2 w = *(const ulonglong2*)(wp + kk*16);
                    unsigned long long p0 = pk2(a0), p1 = pk2(a1);
                    f2fma(A00, p0, w.x); f2fma(A01, p0, w.y);
                    f2fma(A10, p1, w.x); f2fma(A11, p1, w.y);
                }
            }
            __syncthreads();
            unsigned long long* pp = (unsigned long long*)s_stage;
            if (g4 > 0){
                int base = ((g4-1)*64 + t6)*4;
                pp[base]=A00; pp[base+1]=A01; pp[base+2]=A10; pp[base+3]=A11;
            }
            __syncthreads();
            if (g4 == 0){
                #pragma unroll
                for (int gg = 0; gg < 3; gg++){
                    int base = (gg*64 + t6)*4;
                    A00 = ad2(A00, pp[base]);   A01 = ad2(A01, pp[base+1]);
                    A10 = ad2(A10, pp[base+2]); A11 = ad2(A11, pp[base+3]);
                }
                float2 v00 = up2(A00), v01 = up2(A01), v10 = up2(A10), v11 = up2(A11);
                const int c4 = c4b + cq2;
                float4 bi = __ldg(((const float4*)bp2) + c4);
                float4 o0, o1;
                if (seg < 2){
                    o0 = make_float4(fmaxf(v00.x+bi.x,0.f), fmaxf(v00.y+bi.y,0.f),
                                     fmaxf(v01.x+bi.z,0.f), fmaxf(v01.y+bi.w,0.f));
                    o1 = make_float4(fmaxf(v10.x+bi.x,0.f), fmaxf(v10.y+bi.y,0.f),
                                     fmaxf(v11.x+bi.z,0.f), fmaxf(v11.y+bi.w,0.f));
                } else {
                    o0 = make_float4(sigmoidf_(v00.x+bi.x), sigmoidf_(v00.y+bi.y),
                                     sigmoidf_(v01.x+bi.z), sigmoidf_(v01.y+bi.w));
                    o1 = make_float4(sigmoidf_(v10.x+bi.x), sigmoidf_(v10.y+bi.y),
                                     sigmoidf_(v11.x+bi.z), sigmoidf_(v11.y+bi.w));
                }
                int row = RB2*32 + rp2;
                __stcg(((float4*)op2) + row*32 + c4,      o0);
                __stcg(((float4*)op2) + (row+16)*32 + c4, o1);
            }
        }
        gbar();   // k / e / a ready

        // ===== P3 (CTA b): smalls + content addressing + gate/shift/sharpen =====
        {
            __syncthreads();   // P2 scratch reads done before scratch reuse
            if (tid < 128){
                s_kw[tid] = __ldcg(&g_k[b*Mm + tid]);
                s_kr[tid] = __ldcg(&g_k[Bb*Mm + b*Mm + tid]);
                s_e[tid]  = __ldcg(&g_e[b*Mm + tid]);
                s_a[tid]  = __ldcg(&g_a[b*Mm + tid]);
            }
            for (int c = wid; c < 12; c += 8){
                int hd = c / 6, cc = c % 6;
                const float* wp; float bi; int stride;
                if      (cc == 0){ wp = Wb   + hd*Hh;            bi = bb[hd];          stride = 1; }
                else if (cc == 1){ wp = Wg   + hd*Hh;            bi = bg[hd];          stride = 1; }
                else if (cc == 2){ wp = Wgam + hd*Hh;            bi = bgam[hd];        stride = 1; }
                else             { wp = Ws   + hd*Hh*3 + (cc-3); bi = bs[hd*3 + cc-3]; stride = 3; }
                float acc = 0.f;
                for (int h = lane; h < Hh; h += 32)
                    acc += __ldcg(&g_ht[b*Hh + h]) * wp[h*stride];
                #pragma unroll
                for (int off = 16; off; off >>= 1) acc += __shfl_xor_sync(0xffffffffu, acc, off);
                if (lane == 0) s_sm[c] = acc + bi;
            }
            __syncthreads();
            // key norms
            {
                float v  = (tid < 128) ? s_kw[tid] : s_kr[tid - 128];
                float sq = v * v;
                #pragma unroll
                for (int off = 16; off; off >>= 1) sq += __shfl_xor_sync(0xffffffffu, sq, off);
                if (lane == 0) s_red[wid] = sq;
                __syncthreads();
                if (tid == 0){
                    s_red[32] = fmaxf(sqrtf(s_red[0]+s_red[1]+s_red[2]+s_red[3]), EPSf);
                    s_red[33] = fmaxf(sqrtf(s_red[4]+s_red[5]+s_red[6]+s_red[7]), EPSf);
                }
                __syncthreads();
            }
            const float ibw = softplusf(s_sm[0]) / s_red[32];
            const float ibr = softplusf(s_sm[6]) / s_red[33];
            __syncthreads();
            // cosine: dots only (inverse row norms precomputed in P4/init)
            {
                const float4* m4  = ((const float4*)g_mem) + b * (Nn*Mm/4);
                const float4  kw4 = ((float4*)s_kw)[lane];
                const float4  kr4 = ((float4*)s_kr)[lane];
                for (int j = 0; j < 32; j += 2){
                    int n0 = wid*32 + j, n1 = n0 + 1;
                    float4 m0 = m4[n0*32 + lane];
                    float4 m1 = m4[n1*32 + lane];
                    float dw0 = m0.x*kw4.x + m0.y*kw4.y + m0.z*kw4.z + m0.w*kw4.w;
                    float dr0 = m0.x*kr4.x + m0.y*kr4.y + m0.z*kr4.z + m0.w*kr4.w;
                    float dw1 = m1.x*kw4.x + m1.y*kw4.y + m1.z*kw4.z + m1.w*kw4.w;
                    float dr1 = m1.x*kr4.x + m1.y*kr4.y + m1.z*kr4.z + m1.w*kr4.w;
                    #pragma unroll
                    for (int off = 16; off; off >>= 1){
                        dw0 += __shfl_xor_sync(0xffffffffu, dw0, off);
                        dw1 += __shfl_xor_sync(0xffffffffu, dw1, off);
                        dr0 += __shfl_xor_sync(0xffffffffu, dr0, off);
                        dr1 += __shfl_xor_sync(0xffffffffu, dr1, off);
                    }
                    if (lane == 0){
                        s_zw[n0] = dw0 * ibw * s_nrm[n0];  s_zw[n1] = dw1 * ibw * s_nrm[n1];
                        s_zr[n0] = dr0 * ibr * s_nrm[n0];  s_zr[n1] = dr1 * ibr * s_nrm[n1];
                    }
                }
                __syncthreads();
            }
            // per-head weight pipeline (n = tid)
            #pragma unroll 1
            for (int hd = 0; hd < 2; hd++){
                float* sz    = hd ? s_zr : s_zw;
                float* sprev = hd ? s_rw : s_ww;
                float graw = s_sm[hd*6 + 1];
                float gamr = s_sm[hd*6 + 2];
                float r0s  = s_sm[hd*6 + 3], r1s = s_sm[hd*6 + 4], r2s = s_sm[hd*6 + 5];
                float z  = sz[tid];
                float mx = bredMax(z, s_red);
                float ez = expf(z - mx);
                float smv = bredSum(ez, s_red);
                float wc = ez / smv;
                float g  = sigmoidf_(graw);
                s_tmp[tid] = g*wc + (1.f - g)*sprev[tid];
                __syncthreads();
                float m3 = fmaxf(r0s, fmaxf(r1s, r2s));
                float e0 = expf(r0s - m3), e1 = expf(r1s - m3), e2 = expf(r2s - m3);
                float i3 = 1.f / (e0 + e1 + e2);
                float wsh = e0*i3 * s_tmp[(tid + 255) & 255]
                          + e1*i3 * s_tmp[tid]
                          + e2*i3 * s_tmp[(tid + 1) & 255];
                float gamma = fmaxf(gamr, 0.f) + 1.f;
                float wpow  = powf(wsh, gamma);
                float tsum  = bredSum(wpow, s_red);
                sprev[tid]  = wpow / tsum;
            }
            __syncthreads();
        }

        // ===== P4 (CTA b): memory update + rd + next-step inverse row norms =====
        {
            const int mq    = tid & 31;
            const int rbase = tid >> 5;
            const float4 e4 = ((float4*)s_e)[mq];
            const float4 a4 = ((float4*)s_a)[mq];
            float4* m4 = ((float4*)g_mem) + b * (Nn*Mm/4);
            float4 prd = make_float4(0,0,0,0);
            #pragma unroll 4
            for (int it = 0; it < 32; it++){
                int n = it*8 + rbase;
                float wwn = s_ww[n], rwn = s_rw[n];
                float4 mv = m4[n*32 + mq];
                float4 nv;
                nv.x = mv.x*(1.f - wwn*e4.x) + wwn*a4.x;
                nv.y = mv.y*(1.f - wwn*e4.y) + wwn*a4.y;
                nv.z = mv.z*(1.f - wwn*e4.z) + wwn*a4.z;
                nv.w = mv.w*(1.f - wwn*e4.w) + wwn*a4.w;
                m4[n*32 + mq] = nv;
                prd.x += rwn*nv.x; prd.y += rwn*nv.y; prd.z += rwn*nv.z; prd.w += rwn*nv.w;
                float nn = nv.x*nv.x + nv.y*nv.y + nv.z*nv.z + nv.w*nv.w;
                #pragma unroll
                for (int off = 16; off; off >>= 1) nn += __shfl_xor_sync(0xffffffffu, nn, off);
                if (mq == 0) s_nrm[n] = 1.f / fmaxf(sqrtf(nn), EPSf);
            }
            s_prd[tid] = prd;
            __syncthreads();
            if (tid < 32){
                float4 r = s_prd[tid];
                #pragma unroll
                for (int j = 1; j < 8; j++){
                    float4 v = s_prd[tid + 32*j];
                    r.x += v.x; r.y += v.y; r.z += v.z; r.w += v.w;
                }
                __stcg(((float4*)g_rd) + b*32 + tid, r);
            }
        }
    }

    // ===== tail: out[63] = rd_63 @ Wo + bo =====
    gbar();
    if (tid < 128){
        int r = tid >> 2, c = tid & 3;
        int row = RB1*32 + r, col = CB1*4 + c;
        float acc = 0.f;
        #pragma unroll 8
        for (int m = 0; m < 128; m++)
            acc += __ldcg(&g_rd[row*Mm + m]) * __ldg(&Wo[m*Ii + col]);
        out[63*(Bb*Ii) + row*Ii + col] = acc + bo[col];
    }
}

extern "C" void kernel_launch(void* const* d_in, const int* in_sizes, int n_in,
                              void* d_out, int out_size){
    (void)in_sizes; (void)n_in; (void)out_size;
    static int configured = 0;
    if (!configured){
        cudaFuncSetAttribute(ntm_kernel, cudaFuncAttributeMaxDynamicSharedMemorySize,
                             SMEMF * (int)sizeof(float));
        configured = 1;
    }
    ntm_kernel<<<NCTA, NTHR, SMEMF * sizeof(float)>>>(
        (const float*)d_in[0],  (const float*)d_in[1],  (const float*)d_in[2],
        (const float*)d_in[3],  (const float*)d_in[4],  (const float*)d_in[5],
        (const float*)d_in[6],  (const float*)d_in[7],  (const float*)d_in[8],
        (const float*)d_in[9],  (const float*)d_in[10], (const float*)d_in[11],
        (const float*)d_in[12], (const float*)d_in[13], (const float*)d_in[14],
        (const float*)d_in[15], (const float*)d_in[16], (const float*)d_in[17],
        (const float*)d_in[18], (const float*)d_in[19], (const float*)d_in[20],
        (const float*)d_in[21], (const float*)d_in[22],
        (float*)d_out);
}